// round 4
// baseline (speedup 1.0000x reference)
#include <cuda_runtime.h>

#define NBLK 256
#define BE 128            // batch elements per CTA
#define SX 132            // stage row stride in floats (pad vs 128 to dodge conflicts)

#define WB_F   6544                    // phase weight buffer (floats)
#define X_OFF  (WB_F)                  // 20 rows  (node input: 4 lat + 16 var)
#define H1_OFF (X_OFF + 20*SX)         // 64 rows
#define H2_OFF (H1_OFF + 64*SX)        // 64 rows (also z staging rows 0..7)
#define WST_OFF (H2_OFF + 64*SX)       // 16 x 128 selected latent outputs
#define SM_F   (WST_OFF + 16*128)      // = 28128 floats
#define SMEM_BYTES (SM_F*4)            // 112512 B -> 2 CTAs/SM

typedef unsigned long long ull;

__device__ __forceinline__ ull bcast2(float x){ ull r; unsigned u=__float_as_uint(x);
  asm("mov.b64 %0,{%1,%1};":"=l"(r):"r"(u)); return r; }
__device__ __forceinline__ void fma2(ull &a, ull x, ull w){
  asm("fma.rn.f32x2 %0,%1,%2,%0;":"+l"(a):"l"(x),"l"(w)); }
__device__ __forceinline__ float2 unpk(ull a){ unsigned x,y;
  asm("mov.b64 {%0,%1},%2;":"=r"(x),"=r"(y):"l"(a));
  return make_float2(__uint_as_float(x),__uint_as_float(y)); }

__device__ __forceinline__ void cp16(float* dst, const float* __restrict__ src, int n, int tid){
  float4* d=(float4*)dst; const float4* s=(const float4*)src;
  for(int i=tid;i<(n>>2);i+=NBLK) d[i]=s[i];
}

// dense layer -> 64 relu outputs. xs/hout already offset by eg*4. W row stride 64.
template<int IN>
__device__ __forceinline__ void layer64(const float* __restrict__ xs,
                                        const float* __restrict__ W,
                                        const float* __restrict__ bias,
                                        float* __restrict__ hout, int og){
  ull acc[16];
  {
    const ull* bb=(const ull*)(bias+og*8);
    ull b0=bb[0],b1=bb[1],b2=bb[2],b3=bb[3];
#pragma unroll
    for(int e=0;e<4;e++){acc[e*4+0]=b0;acc[e*4+1]=b1;acc[e*4+2]=b2;acc[e*4+3]=b3;}
  }
  const float* wp=W+og*8;
#pragma unroll 4
  for(int i=0;i<IN;i++){
    float4 h=*(const float4*)(xs+i*SX);                 // 4 elems, 1 LDS.128
    ulonglong2 wa=*(const ulonglong2*)(wp+i*64);        // outs 0..3 (pairs)
    ulonglong2 wb=*(const ulonglong2*)(wp+i*64+4);      // outs 4..7
    ull x0=bcast2(h.x),x1=bcast2(h.y),x2=bcast2(h.z),x3=bcast2(h.w);
    fma2(acc[0],x0,wa.x);  fma2(acc[1],x0,wa.y);  fma2(acc[2],x0,wb.x);  fma2(acc[3],x0,wb.y);
    fma2(acc[4],x1,wa.x);  fma2(acc[5],x1,wa.y);  fma2(acc[6],x1,wb.x);  fma2(acc[7],x1,wb.y);
    fma2(acc[8],x2,wa.x);  fma2(acc[9],x2,wa.y);  fma2(acc[10],x2,wb.x); fma2(acc[11],x2,wb.y);
    fma2(acc[12],x3,wa.x); fma2(acc[13],x3,wa.y); fma2(acc[14],x3,wb.x); fma2(acc[15],x3,wb.y);
  }
#pragma unroll
  for(int p=0;p<4;p++){
    float2 f0=unpk(acc[p]),f1=unpk(acc[4+p]),f2=unpk(acc[8+p]),f3=unpk(acc[12+p]);
    float4 v0=make_float4(fmaxf(f0.x,0.f),fmaxf(f1.x,0.f),fmaxf(f2.x,0.f),fmaxf(f3.x,0.f));
    float4 v1=make_float4(fmaxf(f0.y,0.f),fmaxf(f1.y,0.f),fmaxf(f2.y,0.f),fmaxf(f3.y,0.f));
    *(float4*)(hout+(og*8+2*p)*SX)=v0;
    *(float4*)(hout+(og*8+2*p+1)*SX)=v1;
  }
}

// latent final: 64 -> 4 selected outputs (no relu); og redundant, og==0 stores to WST
__device__ __forceinline__ void latfinal(const float* __restrict__ xs,
                                         const float* __restrict__ Wsel,
                                         const float* __restrict__ b4,
                                         float* __restrict__ wst, int og,int eg,int l){
  ull acc[8];
  { const ull* bb=(const ull*)b4;
#pragma unroll
    for(int e=0;e<4;e++){acc[e*2]=bb[0];acc[e*2+1]=bb[1];} }
#pragma unroll 4
  for(int i=0;i<64;i++){
    float4 h=*(const float4*)(xs+i*SX);
    ulonglong2 w=*(const ulonglong2*)(Wsel+i*4);
    fma2(acc[0],bcast2(h.x),w.x); fma2(acc[1],bcast2(h.x),w.y);
    fma2(acc[2],bcast2(h.y),w.x); fma2(acc[3],bcast2(h.y),w.y);
    fma2(acc[4],bcast2(h.z),w.x); fma2(acc[5],bcast2(h.z),w.y);
    fma2(acc[6],bcast2(h.w),w.x); fma2(acc[7],bcast2(h.w),w.y);
  }
  if(og==0){
    float2 f0=unpk(acc[0]),f1=unpk(acc[2]),f2=unpk(acc[4]),f3=unpk(acc[6]);
    float2 g0=unpk(acc[1]),g1=unpk(acc[3]),g2=unpk(acc[5]),g3=unpk(acc[7]);
    *(float4*)(wst+(l*4+0)*128+eg*4)=make_float4(f0.x,f1.x,f2.x,f3.x);
    *(float4*)(wst+(l*4+1)*128+eg*4)=make_float4(f0.y,f1.y,f2.y,f3.y);
    *(float4*)(wst+(l*4+2)*128+eg*4)=make_float4(g0.x,g1.x,g2.x,g3.x);
    *(float4*)(wst+(l*4+3)*128+eg*4)=make_float4(g0.y,g1.y,g2.y,g3.y);
  }
}

// node final: 64 -> 16 (no relu), og covers outs og*2..og*2+1; writes X rows 4..19 + global out
__device__ __forceinline__ void nodefinal(const float* __restrict__ xs,
                                          const float* __restrict__ Wf,
                                          const float* __restrict__ bf,
                                          float* __restrict__ Xst,
                                          float* __restrict__ out,
                                          int og,int eg,int node,int elembase){
  ull acc[4];
  { ull b=((const ull*)bf)[og];
#pragma unroll
    for(int e=0;e<4;e++) acc[e]=b; }
#pragma unroll 4
  for(int i=0;i<64;i++){
    float4 h=*(const float4*)(xs+i*SX);
    ull w=*(const ull*)(Wf+i*16+og*2);
    fma2(acc[0],bcast2(h.x),w); fma2(acc[1],bcast2(h.y),w);
    fma2(acc[2],bcast2(h.z),w); fma2(acc[3],bcast2(h.w),w);
  }
  float2 f0=unpk(acc[0]),f1=unpk(acc[1]),f2=unpk(acc[2]),f3=unpk(acc[3]);
  int o0=og*2, o1=o0+1;
  *(float4*)(Xst+(4+o0)*SX+eg*4)=make_float4(f0.x,f1.x,f2.x,f3.x);
  *(float4*)(Xst+(4+o1)*SX+eg*4)=make_float4(f0.y,f1.y,f2.y,f3.y);
  float* orw=out+(size_t)elembase*113+16*node;
  orw[o0]=f0.x;       orw[o1]=f0.y;
  orw[113+o0]=f1.x;   orw[113+o1]=f1.y;
  orw[226+o0]=f2.x;   orw[226+o1]=f2.y;
  orw[339+o0]=f3.x;   orw[339+o1]=f3.y;
}

// node 7: 64 -> 2 logits, sigmoid + gumbel hard argmax -> out col 112
__device__ __forceinline__ void node7f(const float* __restrict__ xs,
                                       const float* __restrict__ W2,
                                       const float* __restrict__ b2,
                                       const float* __restrict__ gbin,
                                       float* __restrict__ out,
                                       int og,int eg,int elembase){
  ull acc[4];
  { ull b=((const ull*)b2)[0];
#pragma unroll
    for(int e=0;e<4;e++) acc[e]=b; }
#pragma unroll 4
  for(int i=0;i<64;i++){
    float4 h=*(const float4*)(xs+i*SX);
    ull w=*(const ull*)(W2+i*2);
    fma2(acc[0],bcast2(h.x),w); fma2(acc[1],bcast2(h.y),w);
    fma2(acc[2],bcast2(h.z),w); fma2(acc[3],bcast2(h.w),w);
  }
  if(og==0){
#pragma unroll
    for(int e=0;e<4;e++){
      float2 f=unpk(acc[e]);
      float p0=1.f/(1.f+expf(-f.x));
      float p1=1.f/(1.f+expf(-f.y));
      int el=elembase+e;
      float g0=gbin[(size_t)el*2], g1=gbin[(size_t)el*2+1];
      out[(size_t)el*113+112]=(p0+g0>=p1+g1)?1.f:0.f;   // first-index wins ties
    }
  }
}

__global__ __launch_bounds__(NBLK,2)
void gen_kernel(const float *__restrict__ z, const float *__restrict__ data,
                const float *__restrict__ glog, const float *__restrict__ glat,
                const float *__restrict__ gbin,
                const float *__restrict__ LW0, const float *__restrict__ Lb0,
                const float *__restrict__ LW1, const float *__restrict__ Lb1,
                const float *__restrict__ LW2, const float *__restrict__ Lb2,
                const float *__restrict__ NW0, const float *__restrict__ Nb0,
                const float *__restrict__ NW1, const float *__restrict__ Nb1,
                const float *__restrict__ NWf, const float *__restrict__ Nbf,
                const float *__restrict__ W7f, const float *__restrict__ b7f,
                float *__restrict__ out) {
  extern __shared__ float sm[];
  float* wb =sm;
  float* Xs =sm+X_OFF;
  float* H1 =sm+H1_OFF;
  float* H2 =sm+H2_OFF;
  float* WST=sm+WST_OFF;
  const int tid=threadIdx.x, og=tid&7, eg=tid>>3;
  const int elembase=blockIdx.x*BE+eg*4;

  __shared__ int ksel[4];
  if(tid<4){
    const float* a=glog+tid*8; const float* g=glat+tid*8;
    float best=a[0]+g[0]; int bi=0;
#pragma unroll
    for(int k=1;k<8;k++){ float v=a[k]+g[k]; if(v>best){best=v;bi=k;} } // first-max wins
    ksel[tid]=bi;
  }

  // data passthrough (cols 0..31) + var0 (cols 0..15) into X rows 4..19 (feature-major)
#pragma unroll
  for(int e=0;e<4;e++){
    int el=elembase+e;
    const float* dr=data+(size_t)el*113;
    float* orw=out+(size_t)el*113;
#pragma unroll
    for(int k=0;k<4;k++){
      float v=dr[og*4+k];
      orw[og*4+k]=v;
      if(og<4) Xs[(4+og*4+k)*SX+eg*4+e]=v;
    }
  }
  __syncthreads();   // ksel + X var0 ordering

  // ================= latent phase =================
#pragma unroll 1
  for(int l=0;l<4;l++){
    cp16(wb,      LW0+(size_t)l*512, 512, tid);
    cp16(wb+512,  Lb0+l*64,           64, tid);
    cp16(wb+576,  LW1+(size_t)l*4096,4096,tid);
    cp16(wb+4672, Lb1+l*64,           64, tid);
    {
      int k=ksel[l];
      for(int i=tid;i<64;i+=NBLK)
        *(float4*)(wb+4736+4*i)=*(const float4*)(LW2+((size_t)(l*64+i))*32+k*4);
      if(tid<4) wb[4992+tid]=Lb2[l*32+ksel[l]*4+tid];
    }
    { // z -> H2 rows 0..7 (feature-major transpose)
      float v0=z[(size_t)(elembase+0)*32+l*8+og];
      float v1=z[(size_t)(elembase+1)*32+l*8+og];
      float v2=z[(size_t)(elembase+2)*32+l*8+og];
      float v3=z[(size_t)(elembase+3)*32+l*8+og];
      *(float4*)(H2+og*SX+eg*4)=make_float4(v0,v1,v2,v3);
    }
    __syncthreads();
    layer64<8>(H2+eg*4, wb, wb+512, H1+eg*4, og);
    __syncthreads();
    layer64<64>(H1+eg*4, wb+576, wb+4672, H2+eg*4, og);
    __syncthreads();
    latfinal(H2+eg*4, wb+4736, wb+4992, WST, og, eg, l);
    __syncthreads();
  }

  // ================= node chain =================
  const int LAY[6]={0,1,2,3,0,1};   // PARENT_LAT - 1
#pragma unroll 1
  for(int j=0;j<6;j++){
    cp16(wb,      NW0+(size_t)j*1280,1280,tid);
    cp16(wb+1280, Nb0+j*64,           64, tid);
    cp16(wb+1344, NW1+(size_t)j*4096,4096,tid);
    cp16(wb+5440, Nb1+j*64,           64, tid);
    if(j<5){ cp16(wb+5504, NWf+(size_t)j*1024,1024,tid); cp16(wb+6528, Nbf+j*16,16,tid); }
    else   { cp16(wb+5504, W7f,128,tid); if(tid<2) wb[6528+tid]=b7f[tid]; }
    if(og<4)  // lat features -> X rows 0..3
      *(float4*)(Xs+og*SX+eg*4)=*(const float4*)(WST+(LAY[j]*4+og)*128+eg*4);
    __syncthreads();
    layer64<20>(Xs+eg*4, wb, wb+1280, H1+eg*4, og);
    __syncthreads();
    layer64<64>(H1+eg*4, wb+1344, wb+5440, H2+eg*4, og);
    __syncthreads();
    if(j<5) nodefinal(H2+eg*4, wb+5504, wb+6528, Xs, out, og, eg, j+2, elembase);
    else    node7f(H2+eg*4, wb+5504, wb+6528, gbin, out, og, eg, elembase);
    __syncthreads();
  }
}

extern "C" void kernel_launch(void *const *d_in, const int *in_sizes, int n_in,
                              void *d_out, int out_size) {
  (void)in_sizes; (void)n_in; (void)out_size;
  const float *z    = (const float *)d_in[0];
  const float *data = (const float *)d_in[1];
  const float *glog = (const float *)d_in[2];
  const float *glat = (const float *)d_in[3];
  const float *gbin = (const float *)d_in[4];
  const float *LW0  = (const float *)d_in[5];
  const float *Lb0  = (const float *)d_in[6];
  const float *LW1  = (const float *)d_in[7];
  const float *Lb1  = (const float *)d_in[8];
  const float *LW2  = (const float *)d_in[9];
  const float *Lb2  = (const float *)d_in[10];
  const float *NW0  = (const float *)d_in[11];
  const float *Nb0  = (const float *)d_in[12];
  const float *NW1  = (const float *)d_in[13];
  const float *Nb1  = (const float *)d_in[14];
  const float *NWf  = (const float *)d_in[15];
  const float *Nbf  = (const float *)d_in[16];
  const float *W7f  = (const float *)d_in[17];
  const float *b7f  = (const float *)d_in[18];
  float *out = (float *)d_out;

  cudaFuncSetAttribute(gen_kernel, cudaFuncAttributeMaxDynamicSharedMemorySize, SMEM_BYTES);
  gen_kernel<<<131072/BE, NBLK, SMEM_BYTES>>>(
      z, data, glog, glat, gbin, LW0, Lb0, LW1, Lb1, LW2, Lb2,
      NW0, Nb0, NW1, Nb1, NWf, Nbf, W7f, b7f, out);
}

// round 5
// speedup vs baseline: 1.0039x; 1.0039x over previous
#include <cuda_runtime.h>

#define NBLK 256
#define BE 128            // batch elements per CTA
#define SX 132            // stage row stride in floats (pad vs 128 to dodge conflicts)

#define WB_F   6544                    // phase weight buffer (floats)
#define X_OFF  (WB_F)                  // 20 rows  (node input: 4 lat + 16 var)
#define H1_OFF (X_OFF + 20*SX)         // 64 rows
#define H2_OFF (H1_OFF + 64*SX)        // 64 rows (also z staging rows 0..7)
#define WST_OFF (H2_OFF + 64*SX)       // 16 x 128 selected latent outputs
#define SM_F   (WST_OFF + 16*128)      // = 28128 floats
#define SMEM_BYTES (SM_F*4)            // 112512 B -> 2 CTAs/SM

typedef unsigned long long ull;

__device__ __forceinline__ ull bcast2(float x){ ull r; unsigned u=__float_as_uint(x);
  asm("mov.b64 %0,{%1,%1};":"=l"(r):"r"(u)); return r; }
__device__ __forceinline__ void fma2(ull &a, ull x, ull w){
  asm("fma.rn.f32x2 %0,%1,%2,%0;":"+l"(a):"l"(x),"l"(w)); }
__device__ __forceinline__ float2 unpk(ull a){ unsigned x,y;
  asm("mov.b64 {%0,%1},%2;":"=r"(x),"=r"(y):"l"(a));
  return make_float2(__uint_as_float(x),__uint_as_float(y)); }

__device__ __forceinline__ void cp16(float* dst, const float* __restrict__ src, int n, int tid){
  float4* d=(float4*)dst; const float4* s=(const float4*)src;
  for(int i=tid;i<(n>>2);i+=NBLK) d[i]=s[i];
}

// dense layer -> 64 relu outputs. xs/hout already offset by eg*4. W row stride 64.
template<int IN>
__device__ __forceinline__ void layer64(const float* __restrict__ xs,
                                        const float* __restrict__ W,
                                        const float* __restrict__ bias,
                                        float* __restrict__ hout, int og){
  ull acc[16];
  {
    const ull* bb=(const ull*)(bias+og*8);
    ull b0=bb[0],b1=bb[1],b2=bb[2],b3=bb[3];
#pragma unroll
    for(int e=0;e<4;e++){acc[e*4+0]=b0;acc[e*4+1]=b1;acc[e*4+2]=b2;acc[e*4+3]=b3;}
  }
  const float* wp=W+og*8;
#pragma unroll 4
  for(int i=0;i<IN;i++){
    float4 h=*(const float4*)(xs+i*SX);                 // 4 elems, 1 LDS.128
    ulonglong2 wa=*(const ulonglong2*)(wp+i*64);        // outs 0..3 (pairs)
    ulonglong2 wb=*(const ulonglong2*)(wp+i*64+4);      // outs 4..7
    ull x0=bcast2(h.x),x1=bcast2(h.y),x2=bcast2(h.z),x3=bcast2(h.w);
    fma2(acc[0],x0,wa.x);  fma2(acc[1],x0,wa.y);  fma2(acc[2],x0,wb.x);  fma2(acc[3],x0,wb.y);
    fma2(acc[4],x1,wa.x);  fma2(acc[5],x1,wa.y);  fma2(acc[6],x1,wb.x);  fma2(acc[7],x1,wb.y);
    fma2(acc[8],x2,wa.x);  fma2(acc[9],x2,wa.y);  fma2(acc[10],x2,wb.x); fma2(acc[11],x2,wb.y);
    fma2(acc[12],x3,wa.x); fma2(acc[13],x3,wa.y); fma2(acc[14],x3,wb.x); fma2(acc[15],x3,wb.y);
  }
#pragma unroll
  for(int p=0;p<4;p++){
    float2 f0=unpk(acc[p]),f1=unpk(acc[4+p]),f2=unpk(acc[8+p]),f3=unpk(acc[12+p]);
    float4 v0=make_float4(fmaxf(f0.x,0.f),fmaxf(f1.x,0.f),fmaxf(f2.x,0.f),fmaxf(f3.x,0.f));
    float4 v1=make_float4(fmaxf(f0.y,0.f),fmaxf(f1.y,0.f),fmaxf(f2.y,0.f),fmaxf(f3.y,0.f));
    *(float4*)(hout+(og*8+2*p)*SX)=v0;
    *(float4*)(hout+(og*8+2*p+1)*SX)=v1;
  }
}

// latent final: 64 -> 4 selected outputs (no relu); og redundant, og==0 stores to WST
__device__ __forceinline__ void latfinal(const float* __restrict__ xs,
                                         const float* __restrict__ Wsel,
                                         const float* __restrict__ b4,
                                         float* __restrict__ wst, int og,int eg,int l){
  ull acc[8];
  { const ull* bb=(const ull*)b4;
#pragma unroll
    for(int e=0;e<4;e++){acc[e*2]=bb[0];acc[e*2+1]=bb[1];} }
#pragma unroll 4
  for(int i=0;i<64;i++){
    float4 h=*(const float4*)(xs+i*SX);
    ulonglong2 w=*(const ulonglong2*)(Wsel+i*4);
    fma2(acc[0],bcast2(h.x),w.x); fma2(acc[1],bcast2(h.x),w.y);
    fma2(acc[2],bcast2(h.y),w.x); fma2(acc[3],bcast2(h.y),w.y);
    fma2(acc[4],bcast2(h.z),w.x); fma2(acc[5],bcast2(h.z),w.y);
    fma2(acc[6],bcast2(h.w),w.x); fma2(acc[7],bcast2(h.w),w.y);
  }
  if(og==0){
    float2 f0=unpk(acc[0]),f1=unpk(acc[2]),f2=unpk(acc[4]),f3=unpk(acc[6]);
    float2 g0=unpk(acc[1]),g1=unpk(acc[3]),g2=unpk(acc[5]),g3=unpk(acc[7]);
    *(float4*)(wst+(l*4+0)*128+eg*4)=make_float4(f0.x,f1.x,f2.x,f3.x);
    *(float4*)(wst+(l*4+1)*128+eg*4)=make_float4(f0.y,f1.y,f2.y,f3.y);
    *(float4*)(wst+(l*4+2)*128+eg*4)=make_float4(g0.x,g1.x,g2.x,g3.x);
    *(float4*)(wst+(l*4+3)*128+eg*4)=make_float4(g0.y,g1.y,g2.y,g3.y);
  }
}

// node final: 64 -> 16 (no relu), og covers outs og*2..og*2+1; writes X rows 4..19 + global out
__device__ __forceinline__ void nodefinal(const float* __restrict__ xs,
                                          const float* __restrict__ Wf,
                                          const float* __restrict__ bf,
                                          float* __restrict__ Xst,
                                          float* __restrict__ out,
                                          int og,int eg,int node,int elembase){
  ull acc[4];
  { ull b=((const ull*)bf)[og];
#pragma unroll
    for(int e=0;e<4;e++) acc[e]=b; }
#pragma unroll 4
  for(int i=0;i<64;i++){
    float4 h=*(const float4*)(xs+i*SX);
    ull w=*(const ull*)(Wf+i*16+og*2);
    fma2(acc[0],bcast2(h.x),w); fma2(acc[1],bcast2(h.y),w);
    fma2(acc[2],bcast2(h.z),w); fma2(acc[3],bcast2(h.w),w);
  }
  float2 f0=unpk(acc[0]),f1=unpk(acc[1]),f2=unpk(acc[2]),f3=unpk(acc[3]);
  int o0=og*2, o1=o0+1;
  *(float4*)(Xst+(4+o0)*SX+eg*4)=make_float4(f0.x,f1.x,f2.x,f3.x);
  *(float4*)(Xst+(4+o1)*SX+eg*4)=make_float4(f0.y,f1.y,f2.y,f3.y);
  float* orw=out+(size_t)elembase*113+16*node;
  orw[o0]=f0.x;       orw[o1]=f0.y;
  orw[113+o0]=f1.x;   orw[113+o1]=f1.y;
  orw[226+o0]=f2.x;   orw[226+o1]=f2.y;
  orw[339+o0]=f3.x;   orw[339+o1]=f3.y;
}

// node 7: 64 -> 2 logits, sigmoid + gumbel hard argmax -> out col 112
__device__ __forceinline__ void node7f(const float* __restrict__ xs,
                                       const float* __restrict__ W2,
                                       const float* __restrict__ b2,
                                       const float* __restrict__ gbin,
                                       float* __restrict__ out,
                                       int og,int eg,int elembase){
  ull acc[4];
  { ull b=((const ull*)b2)[0];
#pragma unroll
    for(int e=0;e<4;e++) acc[e]=b; }
#pragma unroll 4
  for(int i=0;i<64;i++){
    float4 h=*(const float4*)(xs+i*SX);
    ull w=*(const ull*)(W2+i*2);
    fma2(acc[0],bcast2(h.x),w); fma2(acc[1],bcast2(h.y),w);
    fma2(acc[2],bcast2(h.z),w); fma2(acc[3],bcast2(h.w),w);
  }
  if(og==0){
#pragma unroll
    for(int e=0;e<4;e++){
      float2 f=unpk(acc[e]);
      float p0=1.f/(1.f+expf(-f.x));
      float p1=1.f/(1.f+expf(-f.y));
      int el=elembase+e;
      float g0=gbin[(size_t)el*2], g1=gbin[(size_t)el*2+1];
      out[(size_t)el*113+112]=(p0+g0>=p1+g1)?1.f:0.f;   // first-index wins ties
    }
  }
}

__global__ __launch_bounds__(NBLK,2)
void gen_kernel(const float *__restrict__ z, const float *__restrict__ data,
                const float *__restrict__ glog, const float *__restrict__ glat,
                const float *__restrict__ gbin,
                const float *__restrict__ LW0, const float *__restrict__ Lb0,
                const float *__restrict__ LW1, const float *__restrict__ Lb1,
                const float *__restrict__ LW2, const float *__restrict__ Lb2,
                const float *__restrict__ NW0, const float *__restrict__ Nb0,
                const float *__restrict__ NW1, const float *__restrict__ Nb1,
                const float *__restrict__ NWf, const float *__restrict__ Nbf,
                const float *__restrict__ W7f, const float *__restrict__ b7f,
                float *__restrict__ out) {
  extern __shared__ float sm[];
  float* wb =sm;
  float* Xs =sm+X_OFF;
  float* H1 =sm+H1_OFF;
  float* H2 =sm+H2_OFF;
  float* WST=sm+WST_OFF;
  const int tid=threadIdx.x, og=tid&7, eg=tid>>3;
  const int elembase=blockIdx.x*BE+eg*4;

  __shared__ int ksel[4];
  if(tid<4){
    const float* a=glog+tid*8; const float* g=glat+tid*8;
    float best=a[0]+g[0]; int bi=0;
#pragma unroll
    for(int k=1;k<8;k++){ float v=a[k]+g[k]; if(v>best){best=v;bi=k;} } // first-max wins
    ksel[tid]=bi;
  }

  // data passthrough (cols 0..31) + var0 (cols 0..15) into X rows 4..19 (feature-major)
#pragma unroll
  for(int e=0;e<4;e++){
    int el=elembase+e;
    const float* dr=data+(size_t)el*113;
    float* orw=out+(size_t)el*113;
#pragma unroll
    for(int k=0;k<4;k++){
      float v=dr[og*4+k];
      orw[og*4+k]=v;
      if(og<4) Xs[(4+og*4+k)*SX+eg*4+e]=v;
    }
  }
  __syncthreads();   // ksel + X var0 ordering

  // ================= latent phase =================
#pragma unroll 1
  for(int l=0;l<4;l++){
    cp16(wb,      LW0+(size_t)l*512, 512, tid);
    cp16(wb+512,  Lb0+l*64,           64, tid);
    cp16(wb+576,  LW1+(size_t)l*4096,4096,tid);
    cp16(wb+4672, Lb1+l*64,           64, tid);
    {
      int k=ksel[l];
      for(int i=tid;i<64;i+=NBLK)
        *(float4*)(wb+4736+4*i)=*(const float4*)(LW2+((size_t)(l*64+i))*32+k*4);
      if(tid<4) wb[4992+tid]=Lb2[l*32+ksel[l]*4+tid];
    }
    { // z -> H2 rows 0..7 (feature-major transpose)
      float v0=z[(size_t)(elembase+0)*32+l*8+og];
      float v1=z[(size_t)(elembase+1)*32+l*8+og];
      float v2=z[(size_t)(elembase+2)*32+l*8+og];
      float v3=z[(size_t)(elembase+3)*32+l*8+og];
      *(float4*)(H2+og*SX+eg*4)=make_float4(v0,v1,v2,v3);
    }
    __syncthreads();
    layer64<8>(H2+eg*4, wb, wb+512, H1+eg*4, og);
    __syncthreads();
    layer64<64>(H1+eg*4, wb+576, wb+4672, H2+eg*4, og);
    __syncthreads();
    latfinal(H2+eg*4, wb+4736, wb+4992, WST, og, eg, l);
    __syncthreads();
  }

  // ================= node chain =================
  const int LAY[6]={0,1,2,3,0,1};   // PARENT_LAT - 1
#pragma unroll 1
  for(int j=0;j<6;j++){
    cp16(wb,      NW0+(size_t)j*1280,1280,tid);
    cp16(wb+1280, Nb0+j*64,           64, tid);
    cp16(wb+1344, NW1+(size_t)j*4096,4096,tid);
    cp16(wb+5440, Nb1+j*64,           64, tid);
    if(j<5){ cp16(wb+5504, NWf+(size_t)j*1024,1024,tid); cp16(wb+6528, Nbf+j*16,16,tid); }
    else   { cp16(wb+5504, W7f,128,tid); if(tid<2) wb[6528+tid]=b7f[tid]; }
    if(og<4)  // lat features -> X rows 0..3
      *(float4*)(Xs+og*SX+eg*4)=*(const float4*)(WST+(LAY[j]*4+og)*128+eg*4);
    __syncthreads();
    layer64<20>(Xs+eg*4, wb, wb+1280, H1+eg*4, og);
    __syncthreads();
    layer64<64>(H1+eg*4, wb+1344, wb+5440, H2+eg*4, og);
    __syncthreads();
    if(j<5) nodefinal(H2+eg*4, wb+5504, wb+6528, Xs, out, og, eg, j+2, elembase);
    else    node7f(H2+eg*4, wb+5504, wb+6528, gbin, out, og, eg, elembase);
    __syncthreads();
  }
}

extern "C" void kernel_launch(void *const *d_in, const int *in_sizes, int n_in,
                              void *d_out, int out_size) {
  (void)in_sizes; (void)n_in; (void)out_size;
  const float *z    = (const float *)d_in[0];
  const float *data = (const float *)d_in[1];
  const float *glog = (const float *)d_in[2];
  const float *glat = (const float *)d_in[3];
  const float *gbin = (const float *)d_in[4];
  const float *LW0  = (const float *)d_in[5];
  const float *Lb0  = (const float *)d_in[6];
  const float *LW1  = (const float *)d_in[7];
  const float *Lb1  = (const float *)d_in[8];
  const float *LW2  = (const float *)d_in[9];
  const float *Lb2  = (const float *)d_in[10];
  const float *NW0  = (const float *)d_in[11];
  const float *Nb0  = (const float *)d_in[12];
  const float *NW1  = (const float *)d_in[13];
  const float *Nb1  = (const float *)d_in[14];
  const float *NWf  = (const float *)d_in[15];
  const float *Nbf  = (const float *)d_in[16];
  const float *W7f  = (const float *)d_in[17];
  const float *b7f  = (const float *)d_in[18];
  float *out = (float *)d_out;

  cudaFuncSetAttribute(gen_kernel, cudaFuncAttributeMaxDynamicSharedMemorySize, SMEM_BYTES);
  gen_kernel<<<131072/BE, NBLK, SMEM_BYTES>>>(
      z, data, glog, glat, gbin, LW0, Lb0, LW1, Lb1, LW2, Lb2,
      NW0, Nb0, NW1, Nb1, NWf, Nbf, W7f, b7f, out);
}

// round 6
// speedup vs baseline: 1.6151x; 1.6088x over previous
#include <cuda_runtime.h>

#define NBLK 256
#define BE 128

#define WB_F   6544                    // phase weight buffer (floats)
#define STG_F  WB_F                    // stage: 148 rows x 128 floats
#define XROW   0                       // rows 0..19  (node input: 4 lat + 16 var)
#define H1ROW  20                      // rows 20..83
#define H2ROW  84                      // rows 84..147 (also z rows 84..91)
#define WST_F  (WB_F + 148*128)        // 16 x 128 selected latent outputs
#define SM_F   (WST_F + 16*128)        // 27536 floats
#define SMEM_BYTES (SM_F*4)            // 110144 B -> 2 CTAs/SM

typedef unsigned long long ull;

__device__ __forceinline__ ull bcast2(float x){ ull r; unsigned u=__float_as_uint(x);
  asm("mov.b64 %0,{%1,%1};":"=l"(r):"r"(u)); return r; }
__device__ __forceinline__ void fma2(ull &a, ull x, ull w){
  asm("fma.rn.f32x2 %0,%1,%2,%0;":"+l"(a):"l"(x),"l"(w)); }
__device__ __forceinline__ float2 unpk(ull a){ unsigned x,y;
  asm("mov.b64 {%0,%1},%2;":"=r"(x),"=r"(y):"l"(a));
  return make_float2(__uint_as_float(x),__uint_as_float(y)); }

__device__ __forceinline__ void cp16(float* dst, const float* __restrict__ src, int n, int tid){
  float4* d=(float4*)dst; const float4* s=(const float4*)src;
  for(int i=tid;i<(n>>2);i+=NBLK) d[i]=s[i];
}

// IN inputs -> 64 relu outputs. Warp computes outs [og16,og16+16) for its 64-elem half.
// xin/hout are stage bases already offset by the lane's element offset e2.
// Weight loads are WARP-UNIFORM (1 wf each); act load is LDS.64 full-efficiency.
template<int IN>
__device__ __forceinline__ void layer64(const float* __restrict__ xin,
                                        const float* __restrict__ W,     // [IN][64]
                                        const float* __restrict__ bias,  // [64]
                                        float* __restrict__ hout,
                                        int og16){
  ull acc[8][2];
  {
    const ull* bb=(const ull*)(bias+og16);
#pragma unroll
    for(int op=0;op<8;op++){ ull b=bb[op]; acc[op][0]=b; acc[op][1]=b; }
  }
#pragma unroll 4
  for(int i=0;i<IN;i++){
    float2 h=*(const float2*)(xin + i*128);                      // 2 elems (pair)
    const ulonglong2* wr=(const ulonglong2*)(W + i*64 + og16);   // uniform
    ulonglong2 wA=wr[0], wB=wr[1], wC=wr[2], wD=wr[3];
    ull x0=bcast2(h.x), x1=bcast2(h.y);
    fma2(acc[0][0],x0,wA.x); fma2(acc[0][1],x1,wA.x);
    fma2(acc[1][0],x0,wA.y); fma2(acc[1][1],x1,wA.y);
    fma2(acc[2][0],x0,wB.x); fma2(acc[2][1],x1,wB.x);
    fma2(acc[3][0],x0,wB.y); fma2(acc[3][1],x1,wB.y);
    fma2(acc[4][0],x0,wC.x); fma2(acc[4][1],x1,wC.x);
    fma2(acc[5][0],x0,wC.y); fma2(acc[5][1],x1,wC.y);
    fma2(acc[6][0],x0,wD.x); fma2(acc[6][1],x1,wD.x);
    fma2(acc[7][0],x0,wD.y); fma2(acc[7][1],x1,wD.y);
  }
#pragma unroll
  for(int op=0;op<8;op++){
    float2 e0=unpk(acc[op][0]), e1=unpk(acc[op][1]);
    *(float2*)(hout + (og16+2*op)*128)   = make_float2(fmaxf(e0.x,0.f),fmaxf(e1.x,0.f));
    *(float2*)(hout + (og16+2*op+1)*128) = make_float2(fmaxf(e0.y,0.f),fmaxf(e1.y,0.f));
  }
}

__global__ __launch_bounds__(NBLK,2)
void gen_kernel(const float *__restrict__ z, const float *__restrict__ data,
                const float *__restrict__ glog, const float *__restrict__ glat,
                const float *__restrict__ gbin,
                const float *__restrict__ LW0, const float *__restrict__ Lb0,
                const float *__restrict__ LW1, const float *__restrict__ Lb1,
                const float *__restrict__ LW2, const float *__restrict__ Lb2,
                const float *__restrict__ NW0, const float *__restrict__ Nb0,
                const float *__restrict__ NW1, const float *__restrict__ Nb1,
                const float *__restrict__ NWf, const float *__restrict__ Nbf,
                const float *__restrict__ W7f, const float *__restrict__ b7f,
                float *__restrict__ out) {
  extern __shared__ float sm[];
  float* wb  = sm;
  float* STG = sm + STG_F;
  float* WSTp= sm + WST_F;
  const int tid=threadIdx.x;
  const int w=tid>>5, lane=tid&31;
  const int og16=(w&3)*16;               // output group
  const int e2=(w>>2)*64 + lane*2;       // this lane's element offset within CTA
  const int p=w&3;                       // small-layer pair/quad id
  const int base=blockIdx.x*BE;

  __shared__ int ksel[4];
  if(tid<4){
    const float* a=glog+tid*8; const float* g=glat+tid*8;
    float best=a[0]+g[0]; int bi=0;
#pragma unroll
    for(int k=1;k<8;k++){ float v=a[k]+g[k]; if(v>best){best=v;bi=k;} } // first-max wins
    ksel[tid]=bi;
  }

  // data passthrough (cols 0..31) + var0 (cols 0..15) into X rows 4..19
  {
    int et=tid&127, ch=tid>>7;           // warp-uniform split: warps 0-3 ch0, 4-7 ch1
    int el=base+et;
    const float* dr=data+(size_t)el*113+ch*16;
    float* orw=out+(size_t)el*113+ch*16;
#pragma unroll
    for(int c=0;c<16;c++){
      float v=dr[c]; orw[c]=v;
      if(ch==0) STG[(XROW+4+c)*128+et]=v;
    }
  }
  __syncthreads();   // ksel + var0 staging visible

  // ================= latent phase =================
#pragma unroll 1
  for(int l=0;l<4;l++){
    cp16(wb,      LW0+(size_t)l*512, 512, tid);
    cp16(wb+512,  Lb0+l*64,           64, tid);
    cp16(wb+576,  LW1+(size_t)l*4096,4096,tid);
    cp16(wb+4672, Lb1+l*64,           64, tid);
    {
      int k=ksel[l];
      for(int i=tid;i<64;i+=NBLK)
        *(float4*)(wb+4736+4*i)=*(const float4*)(LW2+((size_t)(l*64+i))*32+k*4);
      if(tid<4) wb[4992+tid]=Lb2[l*32+ksel[l]*4+tid];
    }
    { // z -> H2 rows 0..7 (feature-major transpose)
      int et=tid&127, kh=(tid>>7)*4;
      float4 a=*(const float4*)(z+(size_t)(base+et)*32+l*8+kh);
      STG[(H2ROW+kh+0)*128+et]=a.x;
      STG[(H2ROW+kh+1)*128+et]=a.y;
      STG[(H2ROW+kh+2)*128+et]=a.z;
      STG[(H2ROW+kh+3)*128+et]=a.w;
    }
    __syncthreads();
    layer64<8>(STG+H2ROW*128+e2, wb, wb+512, STG+H1ROW*128+e2, og16);
    __syncthreads();
    layer64<64>(STG+H1ROW*128+e2, wb+576, wb+4672, STG+H2ROW*128+e2, og16);
    __syncthreads();
    // latent final 64->4 (selected): warps with p<2 compute output-pair p for their half
    if(p<2){
      const float* xs=STG+H2ROW*128+e2;
      ull a0,a1;
      { ull b=((const ull*)(wb+4992))[p]; a0=b; a1=b; }
#pragma unroll 4
      for(int i=0;i<64;i++){
        float2 h=*(const float2*)(xs+i*128);
        ull wv=*(const ull*)(wb+4736+i*4+p*2);     // uniform
        fma2(a0,bcast2(h.x),wv); fma2(a1,bcast2(h.y),wv);
      }
      float2 f0=unpk(a0), f1=unpk(a1);
      float* wrow=WSTp+(l*4+2*p)*128+e2;
      *(float2*)(wrow)     = make_float2(f0.x,f1.x);
      *(float2*)(wrow+128) = make_float2(f0.y,f1.y);
    }
    __syncthreads();
  }

  // ================= node chain =================
  const int LAY[6]={0,1,2,3,0,1};   // PARENT_LAT - 1
#pragma unroll 1
  for(int j=0;j<6;j++){
    cp16(wb,      NW0+(size_t)j*1280,1280,tid);
    cp16(wb+1280, Nb0+j*64,           64, tid);
    cp16(wb+1344, NW1+(size_t)j*4096,4096,tid);
    cp16(wb+5440, Nb1+j*64,           64, tid);
    if(j<5){ cp16(wb+5504, NWf+(size_t)j*1024,1024,tid); cp16(wb+6528, Nbf+j*16,16,tid); }
    else   { cp16(wb+5504, W7f,128,tid); if(tid<2) wb[6528+tid]=b7f[tid]; }
    { // lat features -> X rows 0..3
      int et=tid&127;
      for(int r=(tid>>7); r<4; r+=2)
        STG[(XROW+r)*128+et]=WSTp[(LAY[j]*4+r)*128+et];
    }
    __syncthreads();
    layer64<20>(STG+XROW*128+e2, wb, wb+1280, STG+H1ROW*128+e2, og16);
    __syncthreads();
    layer64<64>(STG+H1ROW*128+e2, wb+1344, wb+5440, STG+H2ROW*128+e2, og16);
    __syncthreads();
    if(j<5){
      // node final 64->16: warp quad p computes outs [p*4, p*4+4) for its half
      const float* xs=STG+H2ROW*128+e2;
      ull acc[2][2];
      { const ull* bb=(const ull*)(wb+6528+p*4);
        acc[0][0]=bb[0]; acc[0][1]=bb[0]; acc[1][0]=bb[1]; acc[1][1]=bb[1]; }
#pragma unroll 4
      for(int i=0;i<64;i++){
        float2 h=*(const float2*)(xs+i*128);
        ulonglong2 wv=*(const ulonglong2*)(wb+5504+i*16+p*4);   // uniform
        ull x0=bcast2(h.x), x1=bcast2(h.y);
        fma2(acc[0][0],x0,wv.x); fma2(acc[0][1],x1,wv.x);
        fma2(acc[1][0],x0,wv.y); fma2(acc[1][1],x1,wv.y);
      }
      float2 a0=unpk(acc[0][0]), a1=unpk(acc[0][1]);
      float2 b0=unpk(acc[1][0]), b1=unpk(acc[1][1]);
      float* xr=STG+(XROW+4+p*4)*128+e2;
      *(float2*)(xr)     = make_float2(a0.x,a1.x);
      *(float2*)(xr+128) = make_float2(a0.y,a1.y);
      *(float2*)(xr+256) = make_float2(b0.x,b1.x);
      *(float2*)(xr+384) = make_float2(b0.y,b1.y);
      int node=j+2;
      float* o0=out+(size_t)(base+e2  )*113+16*node+p*4;
      float* o1=out+(size_t)(base+e2+1)*113+16*node+p*4;
      o0[0]=a0.x; o0[1]=a0.y; o0[2]=b0.x; o0[3]=b0.y;
      o1[0]=a1.x; o1[1]=a1.y; o1[2]=b1.x; o1[3]=b1.y;
    } else if(p==0){
      // node 7: 64->2 logits, sigmoid + gumbel hard argmax -> col 112
      const float* xs=STG+H2ROW*128+e2;
      ull a0,a1;
      { ull b=((const ull*)(wb+6528))[0]; a0=b; a1=b; }
#pragma unroll 4
      for(int i=0;i<64;i++){
        float2 h=*(const float2*)(xs+i*128);
        ull wv=*(const ull*)(wb+5504+i*2);          // uniform
        fma2(a0,bcast2(h.x),wv); fma2(a1,bcast2(h.y),wv);
      }
#pragma unroll
      for(int e=0;e<2;e++){
        float2 f=unpk(e?a1:a0);
        float p0=1.f/(1.f+expf(-f.x));
        float p1=1.f/(1.f+expf(-f.y));
        int el=base+e2+e;
        float g0=gbin[(size_t)el*2], g1=gbin[(size_t)el*2+1];
        out[(size_t)el*113+112]=(p0+g0>=p1+g1)?1.f:0.f;   // first-index wins ties
      }
    }
    __syncthreads();
  }
}

extern "C" void kernel_launch(void *const *d_in, const int *in_sizes, int n_in,
                              void *d_out, int out_size) {
  (void)in_sizes; (void)n_in; (void)out_size;
  const float *z    = (const float *)d_in[0];
  const float *data = (const float *)d_in[1];
  const float *glog = (const float *)d_in[2];
  const float *glat = (const float *)d_in[3];
  const float *gbin = (const float *)d_in[4];
  const float *LW0  = (const float *)d_in[5];
  const float *Lb0  = (const float *)d_in[6];
  const float *LW1  = (const float *)d_in[7];
  const float *Lb1  = (const float *)d_in[8];
  const float *LW2  = (const float *)d_in[9];
  const float *Lb2  = (const float *)d_in[10];
  const float *NW0  = (const float *)d_in[11];
  const float *Nb0  = (const float *)d_in[12];
  const float *NW1  = (const float *)d_in[13];
  const float *Nb1  = (const float *)d_in[14];
  const float *NWf  = (const float *)d_in[15];
  const float *Nbf  = (const float *)d_in[16];
  const float *W7f  = (const float *)d_in[17];
  const float *b7f  = (const float *)d_in[18];
  float *out = (float *)d_out;

  cudaFuncSetAttribute(gen_kernel, cudaFuncAttributeMaxDynamicSharedMemorySize, SMEM_BYTES);
  gen_kernel<<<131072/BE, NBLK, SMEM_BYTES>>>(
      z, data, glog, glat, gbin, LW0, Lb0, LW1, Lb1, LW2, Lb2,
      NW0, Nb0, NW1, Nb1, NWf, Nbf, W7f, b7f, out);
}